// round 15
// baseline (speedup 1.0000x reference)
#include <cuda_runtime.h>
#include <cuda_bf16.h>
#include <cstdint>

#define LSEQ 384
#define DSEQ 256
#define H    32
#define P    128

// ---------------------------------------------------------------------------
// scratch (__device__ globals; allocation-free rule)
// ---------------------------------------------------------------------------
__device__ float g_s1[LSEQ * H];
__device__ float g_s2[LSEQ * H];

// A fragments (hi/lo planes), m16n8k16 layout
__device__ uint4 g_Abh[3 * 512],  g_Abl[3 * 512];   // S2  A-frags, per j-tile
__device__ uint4 g_As1h[3 * 512], g_As1l[3 * 512];  // s1  A-frags, per i-tile
// T B-fragments, interleaved {b0h, b1h, b0l, b1l} per slot, 1024 slots (16KB)/i
__device__ uint4 g_Tb[(size_t)LSEQ * 1024];

// ---------------------------------------------------------------------------
// helpers
// ---------------------------------------------------------------------------
__device__ __forceinline__ uint32_t smem_u32(const void* p) {
    uint32_t a;
    asm("{ .reg .u64 t; cvta.to.shared.u64 t, %1; cvt.u32.u64 %0, t; }"
        : "=r"(a) : "l"(p));
    return a;
}
__device__ __forceinline__ void cp16(uint32_t dst, const void* src) {
    asm volatile("cp.async.cg.shared.global [%0], [%1], 16;"
                 :: "r"(dst), "l"(src));
}
#define CP_COMMIT() asm volatile("cp.async.commit_group;" ::: "memory")

// bf16 split: h = packed bf16(x0)|bf16(x1), l = packed residuals
__device__ __forceinline__ void split_pair(float x0, float x1,
                                           uint32_t& h, uint32_t& l) {
    asm("cvt.rn.bf16x2.f32 %0, %1, %2;" : "=r"(h) : "f"(x1), "f"(x0));
    float r0 = x0 - __uint_as_float(h << 16);
    float r1 = x1 - __uint_as_float(h & 0xffff0000u);
    asm("cvt.rn.bf16x2.f32 %0, %1, %2;" : "=r"(l) : "f"(r1), "f"(r0));
}

__device__ __forceinline__ void mma_bf16(float* d, const uint4& a, const uint2& b) {
    asm("mma.sync.aligned.m16n8k16.row.col.f32.bf16.bf16.f32 "
        "{%0,%1,%2,%3},{%4,%5,%6,%7},{%8,%9},{%0,%1,%2,%3};"
        : "+f"(d[0]), "+f"(d[1]), "+f"(d[2]), "+f"(d[3])
        : "r"(a.x), "r"(a.y), "r"(a.z), "r"(a.w), "r"(b.x), "r"(b.y));
}

// 128 x (NT*32) (K=32) bf16x3 mainloop; B interleaved slots
template<int NT>
__device__ __forceinline__ void gemm_compute(
    const uint4* sAH, const uint4* sAL, const uint4* sB,
    int wm, int wn, int lane, float acc[4][NT][4])
{
    #pragma unroll
    for (int kt = 0; kt < 2; kt++) {
        uint2 bh[NT], bl[NT];
        #pragma unroll
        for (int nt = 0; nt < NT; nt++) {
            uint4 v = sB[(kt * 4 * NT + wn * NT + nt) * 32 + lane];
            bh[nt] = make_uint2(v.x, v.y);
            bl[nt] = make_uint2(v.z, v.w);
        }
        #pragma unroll
        for (int mt = 0; mt < 4; mt++) {
            int ai = (kt * 8 + wm * 4 + mt) * 32 + lane;
            uint4 ah = sAH[ai], al = sAL[ai];
            #pragma unroll
            for (int nt = 0; nt < NT; nt++) {
                mma_bf16(acc[mt][nt], ah, bh[nt]);
                mma_bf16(acc[mt][nt], ah, bl[nt]);
                mma_bf16(acc[mt][nt], al, bh[nt]);
            }
        }
    }
}

// Fragment slot for pair-GEMM B, PERMUTED p mapping (matches pair epilogue):
__device__ __forceinline__ int bfrag_slot(int p, int f0) {
    int g = p & 31, wnp = p >> 5;
    int ntp = ((g >> 4) & 1) * 2 + ((g >> 1) & 1);
    int j   = ((g >> 2) & 3) * 2 + (g & 1);
    return ((f0 >> 4) * 16 + wnp * 4 + ntp) * 32 + j * 4 + ((f0 >> 1) & 3);
}

// ---------------------------------------------------------------------------
// lnproj: LayerNorm + both 256->32 projections. Grid 96, 4 rows/CTA.
// Thread = (h = tid>>2 in [0,64), r = tid&3): one FULL dot per thread,
// 64 independent LDG.128 of weights (4 same-h lanes coalesce), X from smem.
// No cross-thread reduction. Weight L2 traffic: 96 x 64KB = 6.1 MB.
// ---------------------------------------------------------------------------
__global__ __launch_bounds__(256) void lnproj_kernel(
    const float* __restrict__ seq,
    const float* __restrict__ gamma, const float* __restrict__ beta,
    const float* __restrict__ w1, const float* __restrict__ b1,
    const float* __restrict__ w2, const float* __restrict__ b2)
{
    __shared__ __align__(16) float Xs[4][DSEQ];
    int tid = threadIdx.x, lane = tid & 31, wid = tid >> 5;
    int i0 = blockIdx.x * 4;

    // LN: warps 0-3, one row each
    if (wid < 4) {
        const float4* srow = (const float4*)(seq + (size_t)(i0 + wid) * DSEQ);
        float4 v0 = __ldg(srow + lane);
        float4 v1 = __ldg(srow + lane + 32);
        float s = v0.x + v0.y + v0.z + v0.w + v1.x + v1.y + v1.z + v1.w;
        float q = v0.x*v0.x + v0.y*v0.y + v0.z*v0.z + v0.w*v0.w
                + v1.x*v1.x + v1.y*v1.y + v1.z*v1.z + v1.w*v1.w;
        #pragma unroll
        for (int o = 16; o; o >>= 1) {
            s += __shfl_xor_sync(0xffffffffu, s, o);
            q += __shfl_xor_sync(0xffffffffu, q, o);
        }
        float mu   = s * (1.f / DSEQ);
        float var  = q * (1.f / DSEQ) - mu * mu;
        float rstd = rsqrtf(var + 1e-5f);
        float4 ga0 = __ldg((const float4*)gamma + lane);
        float4 ga1 = __ldg((const float4*)gamma + lane + 32);
        float4 be0 = __ldg((const float4*)beta + lane);
        float4 be1 = __ldg((const float4*)beta + lane + 32);
        float4 n0, n1;
        n0.x = (v0.x - mu) * rstd * ga0.x + be0.x;
        n0.y = (v0.y - mu) * rstd * ga0.y + be0.y;
        n0.z = (v0.z - mu) * rstd * ga0.z + be0.z;
        n0.w = (v0.w - mu) * rstd * ga0.w + be0.w;
        n1.x = (v1.x - mu) * rstd * ga1.x + be1.x;
        n1.y = (v1.y - mu) * rstd * ga1.y + be1.y;
        n1.z = (v1.z - mu) * rstd * ga1.z + be1.z;
        n1.w = (v1.w - mu) * rstd * ga1.w + be1.w;
        ((float4*)Xs[wid])[lane]      = n0;
        ((float4*)Xs[wid])[lane + 32] = n1;
    }
    __syncthreads();

    // projection: thread (h, r) -> full 256-length dot
    int h = tid >> 2, r = tid & 3;
    const float* W = (h < 32) ? (w1 + h * DSEQ) : (w2 + (h - 32) * DSEQ);
    const float4* Wr = (const float4*)W;
    const float4* Xr = (const float4*)Xs[r];
    float acc = 0.f;
    #pragma unroll 16
    for (int k = 0; k < 64; k++) {
        float4 a = __ldg(Wr + k);
        float4 x = Xr[k];
        acc += a.x * x.x + a.y * x.y + a.z * x.z + a.w * x.w;
    }
    int i = i0 + r;
    if (h < 32) g_s1[i * H + h]        = acc + __ldg(b1 + h);
    else        g_s2[i * H + (h - 32)] = acc + __ldg(b2 + h - 32);
}

// ---------------------------------------------------------------------------
// asplit: pre-build A fragments (hi/lo bf16) for S2 (first half) and s1 (second)
// ---------------------------------------------------------------------------
__global__ __launch_bounds__(256) void asplit_kernel()
{
    int gid = blockIdx.x * 256 + threadIdx.x;      // 0..3071
    int sel = gid >= 1536;
    int idx = sel ? gid - 1536 : gid;
    const float* src = sel ? g_s1 : g_s2;
    uint4* dh = sel ? g_As1h : g_Abh;
    uint4* dl = sel ? g_As1l : g_Abl;

    int lane = idx & 31, rest = idx >> 5;
    int mt = rest & 7, kt = (rest >> 3) & 1, tile = rest >> 4;
    int r = tile * 128 + mt * 16 + (lane >> 2);
    int c = kt * 16 + (lane & 3) * 2;

    float2 v00 = *(const float2*)(src + r * H + c);
    float2 v10 = *(const float2*)(src + (r + 8) * H + c);
    float2 v01 = *(const float2*)(src + r * H + c + 8);
    float2 v11 = *(const float2*)(src + (r + 8) * H + c + 8);
    uint4 hi, lo;
    split_pair(v00.x, v00.y, hi.x, lo.x);
    split_pair(v10.x, v10.y, hi.y, lo.y);
    split_pair(v01.x, v01.y, hi.z, lo.z);
    split_pair(v11.x, v11.y, hi.w, lo.w);
    dh[idx] = hi; dl[idx] = lo;
}

// ---------------------------------------------------------------------------
// tgemm: T[i, n] = sum_d s1[i,d]*w3[n>>5, d*32+(n&31)]  (M=384, N=4096, K=32)
// ---------------------------------------------------------------------------
__global__ __launch_bounds__(256) void tgemm_kernel(const float* __restrict__ w3)
{
    __shared__ float ws[2048];
    __shared__ uint4 sAH[512], sAL[512];
    __shared__ uint4 sB[512];
    int tid = threadIdx.x, lane = tid & 31;
    int itile = blockIdx.x, ntile = blockIdx.y;

    const float4* wsrc = (const float4*)(w3 + (size_t)ntile * 2 * (H * H));
    float4* wdst = (float4*)ws;
    wdst[tid]       = __ldg(wsrc + tid);
    wdst[tid + 256] = __ldg(wsrc + tid + 256);

    sAH[tid]       = g_As1h[itile * 512 + tid];
    sAH[tid + 256] = g_As1h[itile * 512 + tid + 256];
    sAL[tid]       = g_As1l[itile * 512 + tid];
    sAL[tid + 256] = g_As1l[itile * 512 + tid + 256];
    __syncthreads();

    #pragma unroll
    for (int k = 0; k < 2; k++) {
        int t = tid + k * 256;
        int la = t & 31, nt8 = (t >> 5) & 7, kt = t >> 8;
        int nl = nt8 * 8 + (la >> 2);
        int pl = nl >> 5, f = nl & 31;
        int d0 = kt * 16 + (la & 3) * 2;
        const float* wp = ws + pl * 1024;
        float v00 = wp[d0 * H + f];
        float v01 = wp[(d0 + 1) * H + f];
        float v10 = wp[(d0 + 8) * H + f];
        float v11 = wp[(d0 + 9) * H + f];
        uint32_t b0h, b0l, b1h, b1l;
        split_pair(v00, v01, b0h, b0l);
        split_pair(v10, v11, b1h, b1l);
        sB[t] = make_uint4(b0h, b1h, b0l, b1l);
    }

    float acc[4][2][4];
    #pragma unroll
    for (int a = 0; a < 4; a++)
        #pragma unroll
        for (int b = 0; b < 2; b++)
            #pragma unroll
            for (int c = 0; c < 4; c++) acc[a][b][c] = 0.f;
    __syncthreads();

    int wid = tid >> 5, wm = wid >> 2, wn = wid & 3;
    gemm_compute<2>(sAH, sAL, sB, wm, wn, lane, acc);

    int n_base = ntile * 64 + wn * 16 + (lane & 3) * 2;
    int pg = n_base >> 5, f0 = n_base & 31;
    int slot = bfrag_slot(pg, f0);
    #pragma unroll
    for (int mt = 0; mt < 4; mt++) {
        int i = itile * 128 + wm * 64 + mt * 16 + (lane >> 2);
        uint32_t b0h, b0l, b1h, b1l;
        split_pair(acc[mt][0][0], acc[mt][0][1], b0h, b0l);
        split_pair(acc[mt][1][0], acc[mt][1][1], b1h, b1l);
        g_Tb[(size_t)i * 1024 + slot] = make_uint4(b0h, b1h, b0l, b1l);
        split_pair(acc[mt][0][2], acc[mt][0][3], b0h, b0l);
        split_pair(acc[mt][1][2], acc[mt][1][3], b1h, b1l);
        g_Tb[(size_t)(i + 8) * 1024 + slot] = make_uint4(b0h, b1h, b0l, b1l);
    }
}

// ---------------------------------------------------------------------------
// pair (R10 measured-best): CTA = (i-quad, jtile), grid 96x3 = 288,
// 2 CTAs/SM, cp.async streamed B tiles, permuted-p float4 stores.
// ---------------------------------------------------------------------------
#define PAIR_SMEM 81920

__global__ __launch_bounds__(256, 2) void pair_kernel(
    const float* __restrict__ b3, float* __restrict__ out)
{
    extern __shared__ __align__(16) char ps[];
    int tid = threadIdx.x, lane = tid & 31, wid = tid >> 5;
    int wm = wid >> 2, wn = wid & 3, q = lane & 3;
    int iq = blockIdx.x, jt = blockIdx.y;
    int i0 = iq * 4;
    uint32_t sb = smem_u32(ps);

    // A frags (16 KB @ 65536): hi then lo (in commit group 0)
    cp16(sb + 65536 + tid * 16,        &g_Abh[jt * 512 + tid]);
    cp16(sb + 65536 + (tid+256) * 16,  &g_Abh[jt * 512 + tid + 256]);
    cp16(sb + 73728 + tid * 16,        &g_Abl[jt * 512 + tid]);
    cp16(sb + 73728 + (tid+256) * 16,  &g_Abl[jt * 512 + tid + 256]);
    // B frags for 4 i's (16 KB each), one commit-group per i
    #pragma unroll
    for (int it = 0; it < 4; it++) {
        uint32_t base = sb + it * 16384;
        const uint4* src = g_Tb + (size_t)(i0 + it) * 1024;
        cp16(base + tid * 16,             src + tid);
        cp16(base + (tid + 256) * 16,     src + tid + 256);
        cp16(base + (tid + 512) * 16,     src + tid + 512);
        cp16(base + (tid + 768) * 16,     src + tid + 768);
        CP_COMMIT();
    }

    // bias, permuted layout: col = wn*32 + blk*16 + q*4 + {0..3}
    float4 bvf[2];
    bvf[0] = __ldg((const float4*)(b3 + wn * 32 + q * 4));
    bvf[1] = __ldg((const float4*)(b3 + wn * 32 + 16 + q * 4));

    const uint4* sAH = (const uint4*)(ps + 65536);
    const uint4* sAL = (const uint4*)(ps + 73728);

    #pragma unroll
    for (int it = 0; it < 4; it++) {
        if      (it == 0) asm volatile("cp.async.wait_group 3;" ::: "memory");
        else if (it == 1) asm volatile("cp.async.wait_group 2;" ::: "memory");
        else if (it == 2) asm volatile("cp.async.wait_group 1;" ::: "memory");
        else              asm volatile("cp.async.wait_group 0;" ::: "memory");
        __syncthreads();

        float acc[4][4][4];
        #pragma unroll
        for (int blk = 0; blk < 2; blk++)
            #pragma unroll
            for (int mt = 0; mt < 4; mt++) {
                acc[mt][blk*2][0]   = bvf[blk].x; acc[mt][blk*2][1]   = bvf[blk].y;
                acc[mt][blk*2+1][0] = bvf[blk].z; acc[mt][blk*2+1][1] = bvf[blk].w;
                acc[mt][blk*2][2]   = bvf[blk].x; acc[mt][blk*2][3]   = bvf[blk].y;
                acc[mt][blk*2+1][2] = bvf[blk].z; acc[mt][blk*2+1][3] = bvf[blk].w;
            }

        const uint4* sB = (const uint4*)(ps + it * 16384);
        gemm_compute<4>(sAH, sAL, sB, wm, wn, lane, acc);

        #pragma unroll
        for (int mt = 0; mt < 4; mt++) {
            int row = jt * 128 + wm * 64 + mt * 16 + (lane >> 2);
            float* o0 = out + ((size_t)(i0 + it) * LSEQ + row) * P + wn * 32 + q * 4;
            #pragma unroll
            for (int blk = 0; blk < 2; blk++) {
                *(float4*)(o0 + blk * 16) =
                    make_float4(acc[mt][blk*2][0], acc[mt][blk*2][1],
                                acc[mt][blk*2+1][0], acc[mt][blk*2+1][1]);
                *(float4*)(o0 + 8 * P + blk * 16) =
                    make_float4(acc[mt][blk*2][2], acc[mt][blk*2][3],
                                acc[mt][blk*2+1][2], acc[mt][blk*2+1][3]);
            }
        }
    }
}

extern "C" void kernel_launch(void* const* d_in, const int* in_sizes, int n_in,
                              void* d_out, int out_size)
{
    const float* seq   = (const float*)d_in[0];
    const float* gamma = (const float*)d_in[1];
    const float* beta  = (const float*)d_in[2];
    const float* w1    = (const float*)d_in[3];
    const float* b1    = (const float*)d_in[4];
    const float* w2    = (const float*)d_in[5];
    const float* b2    = (const float*)d_in[6];
    const float* w3    = (const float*)d_in[7];
    const float* b3    = (const float*)d_in[8];

    cudaFuncSetAttribute(pair_kernel,
                         cudaFuncAttributeMaxDynamicSharedMemorySize, PAIR_SMEM);

    lnproj_kernel<<<96, 256>>>(seq, gamma, beta, w1, b1, w2, b2);
    asplit_kernel<<<12, 256>>>();
    tgemm_kernel<<<dim3(3, 64), 256>>>(w3);
    pair_kernel<<<dim3(96, 3), 256, PAIR_SMEM>>>(b3, (float*)d_out);
}

// round 16
// speedup vs baseline: 1.1014x; 1.1014x over previous
#include <cuda_runtime.h>
#include <cuda_bf16.h>
#include <cstdint>

#define LSEQ 384
#define DSEQ 256
#define H    32
#define P    128

// ---------------------------------------------------------------------------
// scratch (__device__ globals; allocation-free rule)
// ---------------------------------------------------------------------------
__device__ float g_s1[LSEQ * H];
__device__ float g_s2[LSEQ * H];
// T B-fragments, interleaved {b0h, b1h, b0l, b1l} per slot, 1024 slots (16KB)/i
__device__ uint4 g_Tb[(size_t)LSEQ * 1024];

// ---------------------------------------------------------------------------
// helpers
// ---------------------------------------------------------------------------
__device__ __forceinline__ uint32_t smem_u32(const void* p) {
    uint32_t a;
    asm("{ .reg .u64 t; cvta.to.shared.u64 t, %1; cvt.u32.u64 %0, t; }"
        : "=r"(a) : "l"(p));
    return a;
}
__device__ __forceinline__ void cp16(uint32_t dst, const void* src) {
    asm volatile("cp.async.cg.shared.global [%0], [%1], 16;"
                 :: "r"(dst), "l"(src));
}
#define CP_COMMIT() asm volatile("cp.async.commit_group;" ::: "memory")

// bf16 split: h = packed bf16(x0)|bf16(x1), l = packed residuals
__device__ __forceinline__ void split_pair(float x0, float x1,
                                           uint32_t& h, uint32_t& l) {
    asm("cvt.rn.bf16x2.f32 %0, %1, %2;" : "=r"(h) : "f"(x1), "f"(x0));
    float r0 = x0 - __uint_as_float(h << 16);
    float r1 = x1 - __uint_as_float(h & 0xffff0000u);
    asm("cvt.rn.bf16x2.f32 %0, %1, %2;" : "=r"(l) : "f"(r1), "f"(r0));
}

__device__ __forceinline__ void mma_bf16(float* d, const uint4& a, const uint2& b) {
    asm("mma.sync.aligned.m16n8k16.row.col.f32.bf16.bf16.f32 "
        "{%0,%1,%2,%3},{%4,%5,%6,%7},{%8,%9},{%0,%1,%2,%3};"
        : "+f"(d[0]), "+f"(d[1]), "+f"(d[2]), "+f"(d[3])
        : "r"(a.x), "r"(a.y), "r"(a.z), "r"(a.w), "r"(b.x), "r"(b.y));
}

// 128 x (NT*32) (K=32) bf16x3 mainloop; B interleaved slots
template<int NT>
__device__ __forceinline__ void gemm_compute(
    const uint4* sAH, const uint4* sAL, const uint4* sB,
    int wm, int wn, int lane, float acc[4][NT][4])
{
    #pragma unroll
    for (int kt = 0; kt < 2; kt++) {
        uint2 bh[NT], bl[NT];
        #pragma unroll
        for (int nt = 0; nt < NT; nt++) {
            uint4 v = sB[(kt * 4 * NT + wn * NT + nt) * 32 + lane];
            bh[nt] = make_uint2(v.x, v.y);
            bl[nt] = make_uint2(v.z, v.w);
        }
        #pragma unroll
        for (int mt = 0; mt < 4; mt++) {
            int ai = (kt * 8 + wm * 4 + mt) * 32 + lane;
            uint4 ah = sAH[ai], al = sAL[ai];
            #pragma unroll
            for (int nt = 0; nt < NT; nt++) {
                mma_bf16(acc[mt][nt], ah, bh[nt]);
                mma_bf16(acc[mt][nt], ah, bl[nt]);
                mma_bf16(acc[mt][nt], al, bh[nt]);
            }
        }
    }
}

// Fragment slot for pair-GEMM B, PERMUTED p mapping (matches pair epilogue):
__device__ __forceinline__ int bfrag_slot(int p, int f0) {
    int g = p & 31, wnp = p >> 5;
    int ntp = ((g >> 4) & 1) * 2 + ((g >> 1) & 1);
    int j   = ((g >> 2) & 3) * 2 + (g & 1);
    return ((f0 >> 4) * 16 + wnp * 4 + ntp) * 32 + j * 4 + ((f0 >> 1) & 3);
}

// Build one warp-tile's worth (512 slots) of m16n8k16 A-fragments (hi/lo)
// from a [128 x 32] fp32 row-major block starting at row rbase of src.
// t = kt*256 + mt*32 + lane; thread handles t = tid and tid+256.
__device__ __forceinline__ void build_afrags(
    const float* __restrict__ src, int rbase,
    uint4* sAH, uint4* sAL, int tid)
{
    #pragma unroll
    for (int k = 0; k < 2; k++) {
        int t = tid + k * 256;
        int la = t & 31, mt = (t >> 5) & 7, kt = t >> 8;
        int r = rbase + mt * 16 + (la >> 2);
        int c = kt * 16 + (la & 3) * 2;
        float2 v00 = *(const float2*)(src + r * H + c);
        float2 v10 = *(const float2*)(src + (r + 8) * H + c);
        float2 v01 = *(const float2*)(src + r * H + c + 8);
        float2 v11 = *(const float2*)(src + (r + 8) * H + c + 8);
        uint4 hi, lo;
        split_pair(v00.x, v00.y, hi.x, lo.x);
        split_pair(v10.x, v10.y, hi.y, lo.y);
        split_pair(v01.x, v01.y, hi.z, lo.z);
        split_pair(v11.x, v11.y, hi.w, lo.w);
        sAH[t] = hi; sAL[t] = lo;
    }
}

// ---------------------------------------------------------------------------
// lnproj v3: LayerNorm + both 256->32 projections. Grid 96, 4 rows/CTA.
// Projection: warp w handles h = w*8..w*8+7; per h the warp loads the FULL
// weight row with 2 coalesced LDG.128 (4 sequential lines/instr), X held in
// registers, xor-shfl reduction. All global traffic fully coalesced.
// ---------------------------------------------------------------------------
__global__ __launch_bounds__(256) void lnproj_kernel(
    const float* __restrict__ seq,
    const float* __restrict__ gamma, const float* __restrict__ beta,
    const float* __restrict__ w1, const float* __restrict__ b1,
    const float* __restrict__ w2, const float* __restrict__ b2)
{
    __shared__ __align__(16) float Xs[4][DSEQ];
    int tid = threadIdx.x, lane = tid & 31, wid = tid >> 5;
    int i0 = blockIdx.x * 4;

    // LN: warps 0-3, one row each
    if (wid < 4) {
        const float4* srow = (const float4*)(seq + (size_t)(i0 + wid) * DSEQ);
        float4 v0 = __ldg(srow + lane);
        float4 v1 = __ldg(srow + lane + 32);
        float s = v0.x + v0.y + v0.z + v0.w + v1.x + v1.y + v1.z + v1.w;
        float q = v0.x*v0.x + v0.y*v0.y + v0.z*v0.z + v0.w*v0.w
                + v1.x*v1.x + v1.y*v1.y + v1.z*v1.z + v1.w*v1.w;
        #pragma unroll
        for (int o = 16; o; o >>= 1) {
            s += __shfl_xor_sync(0xffffffffu, s, o);
            q += __shfl_xor_sync(0xffffffffu, q, o);
        }
        float mu   = s * (1.f / DSEQ);
        float var  = q * (1.f / DSEQ) - mu * mu;
        float rstd = rsqrtf(var + 1e-5f);
        float4 ga0 = __ldg((const float4*)gamma + lane);
        float4 ga1 = __ldg((const float4*)gamma + lane + 32);
        float4 be0 = __ldg((const float4*)beta + lane);
        float4 be1 = __ldg((const float4*)beta + lane + 32);
        float4 n0, n1;
        n0.x = (v0.x - mu) * rstd * ga0.x + be0.x;
        n0.y = (v0.y - mu) * rstd * ga0.y + be0.y;
        n0.z = (v0.z - mu) * rstd * ga0.z + be0.z;
        n0.w = (v0.w - mu) * rstd * ga0.w + be0.w;
        n1.x = (v1.x - mu) * rstd * ga1.x + be1.x;
        n1.y = (v1.y - mu) * rstd * ga1.y + be1.y;
        n1.z = (v1.z - mu) * rstd * ga1.z + be1.z;
        n1.w = (v1.w - mu) * rstd * ga1.w + be1.w;
        ((float4*)Xs[wid])[lane]      = n0;
        ((float4*)Xs[wid])[lane + 32] = n1;
    }
    __syncthreads();

    // X rows into registers (per warp, reused across all 8 h)
    float4 x0[4], x1[4];
    #pragma unroll
    for (int r = 0; r < 4; r++) {
        x0[r] = ((const float4*)Xs[r])[lane];
        x1[r] = ((const float4*)Xs[r])[lane + 32];
    }

    #pragma unroll
    for (int hh = 0; hh < 8; hh++) {
        int h = wid * 8 + hh;
        const float* W = (h < 32) ? (w1 + h * DSEQ) : (w2 + (h - 32) * DSEQ);
        float4 a0 = __ldg((const float4*)W + lane);
        float4 a1 = __ldg((const float4*)W + lane + 32);
        float p[4];
        #pragma unroll
        for (int r = 0; r < 4; r++) {
            p[r] = a0.x*x0[r].x + a0.y*x0[r].y + a0.z*x0[r].z + a0.w*x0[r].w
                 + a1.x*x1[r].x + a1.y*x1[r].y + a1.z*x1[r].z + a1.w*x1[r].w;
            #pragma unroll
            for (int o = 16; o; o >>= 1)
                p[r] += __shfl_xor_sync(0xffffffffu, p[r], o);
        }
        if (lane < 4) {
            int i = i0 + lane;
            if (h < 32) g_s1[i * H + h]        = p[lane] + __ldg(b1 + h);
            else        g_s2[i * H + (h - 32)] = p[lane] + __ldg(b2 + h - 32);
        }
    }
}

// ---------------------------------------------------------------------------
// tgemm: T[i, n] = sum_d s1[i,d]*w3[n>>5, d*32+(n&31)]  (M=384, N=4096, K=32)
// A-fragments built in-kernel from g_s1 (asplit deleted).
// ---------------------------------------------------------------------------
__global__ __launch_bounds__(256) void tgemm_kernel(const float* __restrict__ w3)
{
    __shared__ float ws[2048];
    __shared__ uint4 sAH[512], sAL[512];
    __shared__ uint4 sB[512];
    int tid = threadIdx.x, lane = tid & 31;
    int itile = blockIdx.x, ntile = blockIdx.y;

    const float4* wsrc = (const float4*)(w3 + (size_t)ntile * 2 * (H * H));
    float4* wdst = (float4*)ws;
    wdst[tid]       = __ldg(wsrc + tid);
    wdst[tid + 256] = __ldg(wsrc + tid + 256);

    build_afrags(g_s1, itile * 128, sAH, sAL, tid);
    __syncthreads();

    #pragma unroll
    for (int k = 0; k < 2; k++) {
        int t = tid + k * 256;
        int la = t & 31, nt8 = (t >> 5) & 7, kt = t >> 8;
        int nl = nt8 * 8 + (la >> 2);
        int pl = nl >> 5, f = nl & 31;
        int d0 = kt * 16 + (la & 3) * 2;
        const float* wp = ws + pl * 1024;
        float v00 = wp[d0 * H + f];
        float v01 = wp[(d0 + 1) * H + f];
        float v10 = wp[(d0 + 8) * H + f];
        float v11 = wp[(d0 + 9) * H + f];
        uint32_t b0h, b0l, b1h, b1l;
        split_pair(v00, v01, b0h, b0l);
        split_pair(v10, v11, b1h, b1l);
        sB[t] = make_uint4(b0h, b1h, b0l, b1l);
    }

    float acc[4][2][4];
    #pragma unroll
    for (int a = 0; a < 4; a++)
        #pragma unroll
        for (int b = 0; b < 2; b++)
            #pragma unroll
            for (int c = 0; c < 4; c++) acc[a][b][c] = 0.f;
    __syncthreads();

    int wid = tid >> 5, wm = wid >> 2, wn = wid & 3;
    gemm_compute<2>(sAH, sAL, sB, wm, wn, lane, acc);

    int n_base = ntile * 64 + wn * 16 + (lane & 3) * 2;
    int pg = n_base >> 5, f0 = n_base & 31;
    int slot = bfrag_slot(pg, f0);
    #pragma unroll
    for (int mt = 0; mt < 4; mt++) {
        int i = itile * 128 + wm * 64 + mt * 16 + (lane >> 2);
        uint32_t b0h, b0l, b1h, b1l;
        split_pair(acc[mt][0][0], acc[mt][0][1], b0h, b0l);
        split_pair(acc[mt][1][0], acc[mt][1][1], b1h, b1l);
        g_Tb[(size_t)i * 1024 + slot] = make_uint4(b0h, b1h, b0l, b1l);
        split_pair(acc[mt][0][2], acc[mt][0][3], b0h, b0l);
        split_pair(acc[mt][1][2], acc[mt][1][3], b1h, b1l);
        g_Tb[(size_t)(i + 8) * 1024 + slot] = make_uint4(b0h, b1h, b0l, b1l);
    }
}

// ---------------------------------------------------------------------------
// pair: CTA = (i-quad, jtile), grid 96x3 = 288, 2 CTAs/SM.
// B tiles streamed via cp.async (4 groups); S2 A-fragments built in-kernel
// from g_s2 (overlapping the async stream). Permuted-p float4 stores.
// ---------------------------------------------------------------------------
#define PAIR_SMEM 81920

__global__ __launch_bounds__(256, 2) void pair_kernel(
    const float* __restrict__ b3, float* __restrict__ out)
{
    extern __shared__ __align__(16) char ps[];
    int tid = threadIdx.x, lane = tid & 31, wid = tid >> 5;
    int wm = wid >> 2, wn = wid & 3, q = lane & 3;
    int iq = blockIdx.x, jt = blockIdx.y;
    int i0 = iq * 4;
    uint32_t sb = smem_u32(ps);

    // B frags for 4 i's (16 KB each), one commit-group per i
    #pragma unroll
    for (int it = 0; it < 4; it++) {
        uint32_t base = sb + it * 16384;
        const uint4* src = g_Tb + (size_t)(i0 + it) * 1024;
        cp16(base + tid * 16,             src + tid);
        cp16(base + (tid + 256) * 16,     src + tid + 256);
        cp16(base + (tid + 512) * 16,     src + tid + 512);
        cp16(base + (tid + 768) * 16,     src + tid + 768);
        CP_COMMIT();
    }

    // A frags built locally from g_s2 (LDGs overlap the cp.async stream)
    uint4* pAH = (uint4*)(ps + 65536);
    uint4* pAL = (uint4*)(ps + 73728);
    build_afrags(g_s2, jt * 128, pAH, pAL, tid);

    // bias, permuted layout: col = wn*32 + blk*16 + q*4 + {0..3}
    float4 bvf[2];
    bvf[0] = __ldg((const float4*)(b3 + wn * 32 + q * 4));
    bvf[1] = __ldg((const float4*)(b3 + wn * 32 + 16 + q * 4));

    const uint4* sAH = pAH;
    const uint4* sAL = pAL;

    #pragma unroll
    for (int it = 0; it < 4; it++) {
        if      (it == 0) asm volatile("cp.async.wait_group 3;" ::: "memory");
        else if (it == 1) asm volatile("cp.async.wait_group 2;" ::: "memory");
        else if (it == 2) asm volatile("cp.async.wait_group 1;" ::: "memory");
        else              asm volatile("cp.async.wait_group 0;" ::: "memory");
        __syncthreads();

        float acc[4][4][4];
        #pragma unroll
        for (int blk = 0; blk < 2; blk++)
            #pragma unroll
            for (int mt = 0; mt < 4; mt++) {
                acc[mt][blk*2][0]   = bvf[blk].x; acc[mt][blk*2][1]   = bvf[blk].y;
                acc[mt][blk*2+1][0] = bvf[blk].z; acc[mt][blk*2+1][1] = bvf[blk].w;
                acc[mt][blk*2][2]   = bvf[blk].x; acc[mt][blk*2][3]   = bvf[blk].y;
                acc[mt][blk*2+1][2] = bvf[blk].z; acc[mt][blk*2+1][3] = bvf[blk].w;
            }

        const uint4* sB = (const uint4*)(ps + it * 16384);
        gemm_compute<4>(sAH, sAL, sB, wm, wn, lane, acc);

        #pragma unroll
        for (int mt = 0; mt < 4; mt++) {
            int row = jt * 128 + wm * 64 + mt * 16 + (lane >> 2);
            float* o0 = out + ((size_t)(i0 + it) * LSEQ + row) * P + wn * 32 + q * 4;
            #pragma unroll
            for (int blk = 0; blk < 2; blk++) {
                *(float4*)(o0 + blk * 16) =
                    make_float4(acc[mt][blk*2][0], acc[mt][blk*2][1],
                                acc[mt][blk*2+1][0], acc[mt][blk*2+1][1]);
                *(float4*)(o0 + 8 * P + blk * 16) =
                    make_float4(acc[mt][blk*2][2], acc[mt][blk*2][3],
                                acc[mt][blk*2+1][2], acc[mt][blk*2+1][3]);
            }
        }
    }
}

extern "C" void kernel_launch(void* const* d_in, const int* in_sizes, int n_in,
                              void* d_out, int out_size)
{
    const float* seq   = (const float*)d_in[0];
    const float* gamma = (const float*)d_in[1];
    const float* beta  = (const float*)d_in[2];
    const float* w1    = (const float*)d_in[3];
    const float* b1    = (const float*)d_in[4];
    const float* w2    = (const float*)d_in[5];
    const float* b2    = (const float*)d_in[6];
    const float* w3    = (const float*)d_in[7];
    const float* b3    = (const float*)d_in[8];

    cudaFuncSetAttribute(pair_kernel,
                         cudaFuncAttributeMaxDynamicSharedMemorySize, PAIR_SMEM);

    lnproj_kernel<<<96, 256>>>(seq, gamma, beta, w1, b1, w2, b2);
    tgemm_kernel<<<dim3(3, 64), 256>>>(w3);
    pair_kernel<<<dim3(96, 3), 256, PAIR_SMEM>>>(b3, (float*)d_out);
}